// round 2
// baseline (speedup 1.0000x reference)
#include <cuda_runtime.h>
#include <cstdint>
#include <cmath>

#define B_ 64
#define T_ 1024
#define D_ 512
#define H_ 768
#define G4 3072   // 4*H
#define OW 1536   // 2*H
#define NBLK 48   // column blocks per direction

// ---------------- scratch (device globals: allocation-free rule) ----------
__device__ float    g_xz[2][(size_t)T_ * B_ * G4];   // gate-permuted input projections, fp32
__device__ uint32_t g_Wp[2][D_ * G4];                // permuted W, tf32 bits
__device__ uint32_t g_Up[2][H_ * G4];                // permuted U, tf32 bits
__device__ uint32_t g_h[2][2][B_ * H_];              // [dir][phase], tf32 bits
__device__ float    g_c[2][B_ * H_];
__device__ unsigned g_bar_cnt[2];                    // barrier arrival counters (start 0)
__device__ unsigned g_bar_gen[2];                    // barrier generation (monotonic)

// ---------------- helpers --------------------------------------------------
__device__ __forceinline__ uint32_t f2tf32(float f) {
    uint32_t r;
    asm("cvt.rna.tf32.f32 %0, %1;" : "=r"(r) : "f"(f));
    return r;
}

__device__ __forceinline__ void mma_tf32(float* c, const uint32_t* a, const uint32_t* b) {
    asm volatile(
        "mma.sync.aligned.m16n8k8.row.col.f32.tf32.tf32.f32 "
        "{%0,%1,%2,%3}, {%4,%5,%6,%7}, {%8,%9}, {%0,%1,%2,%3};"
        : "+f"(c[0]), "+f"(c[1]), "+f"(c[2]), "+f"(c[3])
        : "r"(a[0]), "r"(a[1]), "r"(a[2]), "r"(a[3]), "r"(b[0]), "r"(b[1]));
}

// ---------------- prep kernels ---------------------------------------------
// Permuted column: n = 4*j + g  maps from source column g*H + j.
__global__ void prep_w(const float* __restrict__ Wf, const float* __restrict__ Wb) {
    int i = blockIdx.x * 256 + threadIdx.x;
    if (i >= D_ * G4) return;
    int n = i % G4;
    int base = i - n;
    int src = base + ((n & 3) * H_ + (n >> 2));
    g_Wp[0][i] = f2tf32(Wf[src]);
    g_Wp[1][i] = f2tf32(Wb[src]);
}

__global__ void prep_u(const float* __restrict__ Uf, const float* __restrict__ Ub) {
    int i = blockIdx.x * 256 + threadIdx.x;
    if (i >= H_ * G4) return;
    int n = i % G4;
    int base = i - n;
    int src = base + ((n & 3) * H_ + (n >> 2));
    g_Up[0][i] = f2tf32(Uf[src]);
    g_Up[1][i] = f2tf32(Ub[src]);
}

__global__ void prep_state() {
    int i = blockIdx.x * 256 + threadIdx.x;
    if (i >= B_ * H_) return;
    g_h[0][0][i] = 0u; g_h[0][1][i] = 0u;
    g_h[1][0][i] = 0u; g_h[1][1][i] = 0u;
    g_c[0][i] = 0.0f;  g_c[1][i] = 0.0f;
}

// ---------------- input projection GEMM ------------------------------------
// GEMM: A = x viewed as [M=B*T, K=D] (row = b*T + t), B = g_Wp[dir] [D, G4],
// out -> g_xz[dir][(t*B + b)*G4 + n] + bias_perm[n].
__global__ __launch_bounds__(256) void proj_kernel(const float* __restrict__ x,
                                                   const float* __restrict__ bfv,
                                                   const float* __restrict__ bbv) {
    __shared__ uint32_t As[128][17];
    __shared__ uint32_t Bs[16][132];

    const int dir = blockIdx.z;
    const uint32_t* __restrict__ Wp = g_Wp[dir];
    const float* __restrict__ bias = dir ? bbv : bfv;
    const int row0 = blockIdx.x * 128;
    const int n0   = blockIdx.y * 128;
    const int tid  = threadIdx.x;
    const int lane = tid & 31;
    const int warp = tid >> 5;
    const int wm = warp & 1;
    const int wn = warp >> 1;

    float acc[4][4][4];
    #pragma unroll
    for (int mi = 0; mi < 4; mi++)
        #pragma unroll
        for (int ni = 0; ni < 4; ni++)
            #pragma unroll
            for (int e = 0; e < 4; e++) acc[mi][ni][e] = 0.0f;

    for (int k0 = 0; k0 < D_; k0 += 16) {
        {
            int r = tid >> 2;
            int c4 = (tid & 3) * 4;
            #pragma unroll
            for (int rr = 0; rr < 2; rr++) {
                int row = r + rr * 64;
                float4 v = *(const float4*)(x + (size_t)(row0 + row) * D_ + k0 + c4);
                As[row][c4 + 0] = f2tf32(v.x);
                As[row][c4 + 1] = f2tf32(v.y);
                As[row][c4 + 2] = f2tf32(v.z);
                As[row][c4 + 3] = f2tf32(v.w);
            }
        }
        {
            int r = tid >> 5;
            int c4 = (tid & 31) * 4;
            #pragma unroll
            for (int rr = 0; rr < 2; rr++) {
                int row = r + rr * 8;
                uint4 v = *(const uint4*)(Wp + (size_t)(k0 + row) * G4 + n0 + c4);
                Bs[row][c4 + 0] = v.x;
                Bs[row][c4 + 1] = v.y;
                Bs[row][c4 + 2] = v.z;
                Bs[row][c4 + 3] = v.w;
            }
        }
        __syncthreads();

        #pragma unroll
        for (int kk = 0; kk < 16; kk += 8) {
            uint32_t af[4][4];
            uint32_t bfr[4][2];
            #pragma unroll
            for (int mi = 0; mi < 4; mi++) {
                int rb = wm * 64 + mi * 16 + (lane >> 2);
                int cb = kk + (lane & 3);
                af[mi][0] = As[rb][cb];
                af[mi][1] = As[rb + 8][cb];
                af[mi][2] = As[rb][cb + 4];
                af[mi][3] = As[rb + 8][cb + 4];
            }
            #pragma unroll
            for (int ni = 0; ni < 4; ni++) {
                int nb = wn * 32 + ni * 8 + (lane >> 2);
                int kb = kk + (lane & 3);
                bfr[ni][0] = Bs[kb][nb];
                bfr[ni][1] = Bs[kb + 4][nb];
            }
            #pragma unroll
            for (int mi = 0; mi < 4; mi++)
                #pragma unroll
                for (int ni = 0; ni < 4; ni++)
                    mma_tf32(acc[mi][ni], af[mi], bfr[ni]);
        }
        __syncthreads();
    }

    #pragma unroll
    for (int mi = 0; mi < 4; mi++) {
        #pragma unroll
        for (int ni = 0; ni < 4; ni++) {
            int rl = wm * 64 + mi * 16 + (lane >> 2);
            int cl = wn * 32 + ni * 8 + 2 * (lane & 3);
            #pragma unroll
            for (int e = 0; e < 4; e++) {
                int rr = rl + (e >> 1) * 8;
                int cc = cl + (e & 1);
                int grow = row0 + rr;
                int b = grow >> 10;
                int t = grow & (T_ - 1);
                int n = n0 + cc;
                float v = acc[mi][ni][e] + __ldg(&bias[(n & 3) * H_ + (n >> 2)]);
                g_xz[dir][((size_t)t * B_ + b) * G4 + n] = v;
            }
        }
    }
}

// ---------------- persistent recurrent kernel -------------------------------
// grid (NBLK, 2). Each block owns a 64-wide z-column tile (16 h cols x 4 gates)
// and keeps its U tile (768x64 tf32, XOR-swizzled) in shared memory for all T
// steps. Per-direction software grid barrier between steps.
#define SMEM_U_WORDS (H_ * 64)
#define SMEM_A_WORDS (2 * 64 * 17)
#define SMEM_BYTES   ((SMEM_U_WORDS + SMEM_A_WORDS) * 4 + 64 * 68 * 4)

__global__ __launch_bounds__(256, 1) void rnn_persistent(float* __restrict__ out) {
    extern __shared__ char smem_raw[];
    uint32_t* Us = (uint32_t*)smem_raw;                                   // [H_][64] swizzled
    uint32_t (*As)[64][17] = (uint32_t (*)[64][17])(smem_raw + SMEM_U_WORDS * 4);
    float (*Zs)[68] = (float (*)[68])(smem_raw + (SMEM_U_WORDS + SMEM_A_WORDS) * 4);

    const int dir = blockIdx.y;
    const int n0  = blockIdx.x * 64;
    const int tid = threadIdx.x;
    const int lane = tid & 31;
    const int warp = tid >> 5;
    const int wm = warp & 1;
    const int wn = warp >> 1;

    const uint32_t* __restrict__ Up = g_Up[dir];

    // ---- load U tile into smem once (swizzle: col ^= (k&3)<<3) ----
    for (int i = tid; i < H_ * 16; i += 256) {      // 16 uint4 per k-row
        int k  = i >> 4;
        int n4 = (i & 15) * 4;
        uint4 v = *(const uint4*)(Up + (size_t)k * G4 + n0 + n4);
        int sc = n4 ^ ((k & 3) << 3);
        *(uint4*)&Us[k * 64 + sc] = v;
    }
    __syncthreads();

    const int sw = (lane & 3) << 3;  // B-fragment swizzle, constant per lane
    unsigned bar_gen_seen = g_bar_gen[dir];

    for (int t = 0; t < T_; t++) {
        const uint32_t* __restrict__ hp = g_h[dir][t & 1];
        uint32_t* __restrict__ hnext = g_h[dir][(t + 1) & 1];

        float acc[2][2][4];
        #pragma unroll
        for (int mi = 0; mi < 2; mi++)
            #pragma unroll
            for (int ni = 0; ni < 2; ni++)
                #pragma unroll
                for (int e = 0; e < 4; e++) acc[mi][ni][e] = 0.0f;

        // prologue: load first h tile (L2-only loads: produced by other SMs)
        {
            int r = tid >> 2;
            int c4 = (tid & 3) * 4;
            uint4 v = __ldcg((const uint4*)(hp + (size_t)r * H_ + c4));
            As[0][r][c4 + 0] = v.x; As[0][r][c4 + 1] = v.y;
            As[0][r][c4 + 2] = v.z; As[0][r][c4 + 3] = v.w;
        }

        int buf = 0;
        for (int k0 = 0; k0 < H_; k0 += 16) {
            __syncthreads();
            if (k0 + 16 < H_) {
                int r = tid >> 2;
                int c4 = (tid & 3) * 4;
                uint4 v = __ldcg((const uint4*)(hp + (size_t)r * H_ + k0 + 16 + c4));
                As[buf ^ 1][r][c4 + 0] = v.x; As[buf ^ 1][r][c4 + 1] = v.y;
                As[buf ^ 1][r][c4 + 2] = v.z; As[buf ^ 1][r][c4 + 3] = v.w;
            }

            #pragma unroll
            for (int kk = 0; kk < 16; kk += 8) {
                uint32_t af[2][4];
                uint32_t bfr[2][2];
                #pragma unroll
                for (int mi = 0; mi < 2; mi++) {
                    int rb = wm * 32 + mi * 16 + (lane >> 2);
                    int cb = kk + (lane & 3);
                    af[mi][0] = As[buf][rb][cb];
                    af[mi][1] = As[buf][rb + 8][cb];
                    af[mi][2] = As[buf][rb][cb + 4];
                    af[mi][3] = As[buf][rb + 8][cb + 4];
                }
                #pragma unroll
                for (int ni = 0; ni < 2; ni++) {
                    int nb = wn * 16 + ni * 8 + (lane >> 2);
                    int kb = k0 + kk + (lane & 3);
                    bfr[ni][0] = Us[kb * 64 + (nb ^ sw)];
                    bfr[ni][1] = Us[(kb + 4) * 64 + (nb ^ sw)];
                }
                #pragma unroll
                for (int mi = 0; mi < 2; mi++)
                    #pragma unroll
                    for (int ni = 0; ni < 2; ni++)
                        mma_tf32(acc[mi][ni], af[mi], bfr[ni]);
            }
            buf ^= 1;
        }

        // park z tile in smem
        #pragma unroll
        for (int mi = 0; mi < 2; mi++)
            #pragma unroll
            for (int ni = 0; ni < 2; ni++)
                #pragma unroll
                for (int e = 0; e < 4; e++) {
                    int rr = wm * 32 + mi * 16 + (lane >> 2) + (e >> 1) * 8;
                    int cc = wn * 16 + ni * 8 + 2 * (lane & 3) + (e & 1);
                    Zs[rr][cc] = acc[mi][ni][e];
                }
        __syncthreads();

        const int tt = dir ? (T_ - 1 - t) : t;
        const float* __restrict__ xz = g_xz[dir] + (size_t)tt * B_ * G4;

        #pragma unroll
        for (int q = 0; q < 4; q++) {
            int cell = tid + q * 256;     // 0..1023 = 64 batch x 16 h-cols
            int b  = cell >> 4;
            int jj = cell & 15;
            int nl = jj * 4;
            const float* xzp = xz + (size_t)b * G4 + n0 + nl;
            float zi = Zs[b][nl + 0] + __ldg(xzp + 0);
            float zf = Zs[b][nl + 1] + __ldg(xzp + 1);
            float zg = Zs[b][nl + 2] + __ldg(xzp + 2);
            float zo = Zs[b][nl + 3] + __ldg(xzp + 3);

            float ig = 1.0f / (1.0f + expf(-zi));
            float fg = 1.0f / (1.0f + expf(-zf));
            float og = 1.0f / (1.0f + expf(-zo));

            int j = (n0 >> 2) + jj;
            int sidx = b * H_ + j;
            float c = fg * g_c[dir][sidx] + ig * tanhf(zg);
            g_c[dir][sidx] = c;
            float h = og * tanhf(c);
            hnext[sidx] = f2tf32(h);
            out[((size_t)b * T_ + tt) * OW + dir * H_ + j] = h;
        }

        // ---- per-direction grid barrier (sense-reversing on generation) ----
        __syncthreads();
        if (tid == 0) {
            __threadfence();
            unsigned old = atomicAdd(&g_bar_cnt[dir], 1u);
            if (old == NBLK - 1) {
                g_bar_cnt[dir] = 0;
                __threadfence();
                atomicExch(&g_bar_gen[dir], bar_gen_seen + 1);
            } else {
                while (atomicAdd(&g_bar_gen[dir], 0u) == bar_gen_seen) { }
            }
        }
        bar_gen_seen++;
        __syncthreads();
    }
}

// ---------------- launch ----------------------------------------------------
extern "C" void kernel_launch(void* const* d_in, const int* in_sizes, int n_in,
                              void* d_out, int out_size) {
    (void)in_sizes; (void)n_in; (void)out_size;
    const float* x  = (const float*)d_in[0];
    const float* Wf = (const float*)d_in[1];
    const float* Uf = (const float*)d_in[2];
    const float* bf = (const float*)d_in[3];
    const float* Wb = (const float*)d_in[4];
    const float* Ub = (const float*)d_in[5];
    const float* bb = (const float*)d_in[6];
    float* out = (float*)d_out;

    cudaFuncSetAttribute(rnn_persistent,
                         cudaFuncAttributeMaxDynamicSharedMemorySize, SMEM_BYTES);

    prep_w<<<(D_ * G4 + 255) / 256, 256>>>(Wf, Wb);
    prep_u<<<(H_ * G4 + 255) / 256, 256>>>(Uf, Ub);
    prep_state<<<(B_ * H_ + 255) / 256, 256>>>();

    proj_kernel<<<dim3(512, 24, 2), 256>>>(x, bf, bb);

    rnn_persistent<<<dim3(NBLK, 2), 256, SMEM_BYTES>>>(out);
}

// round 3
// speedup vs baseline: 1.9302x; 1.9302x over previous
#include <cuda_runtime.h>
#include <cstdint>
#include <cmath>

#define B_ 64
#define T_ 1024
#define D_ 512
#define H_ 768
#define G4 3072   // 4*H
#define OW 1536   // 2*H
#define NBLK 48   // column blocks per direction

// ---------------- scratch (device globals: allocation-free rule) ----------
__device__ float    g_xz[2][(size_t)T_ * B_ * G4];   // gate-permuted input projections, fp32
__device__ uint32_t g_Wp[2][D_ * G4];                // permuted W, tf32 bits
__device__ uint32_t g_Up[2][H_ * G4];                // permuted U, tf32 bits
__device__ uint32_t g_h[2][2][B_ * H_];              // [dir][phase], tf32 bits
__device__ unsigned g_bar_cnt[2];                    // barrier arrival counters
__device__ unsigned g_bar_gen[2];                    // barrier generation (monotonic)

// ---------------- helpers --------------------------------------------------
__device__ __forceinline__ uint32_t f2tf32(float f) {
    uint32_t r;
    asm("cvt.rna.tf32.f32 %0, %1;" : "=r"(r) : "f"(f));
    return r;
}

__device__ __forceinline__ void mma_tf32(float* c, const uint32_t* a, const uint32_t* b) {
    asm volatile(
        "mma.sync.aligned.m16n8k8.row.col.f32.tf32.tf32.f32 "
        "{%0,%1,%2,%3}, {%4,%5,%6,%7}, {%8,%9}, {%0,%1,%2,%3};"
        : "+f"(c[0]), "+f"(c[1]), "+f"(c[2]), "+f"(c[3])
        : "r"(a[0]), "r"(a[1]), "r"(a[2]), "r"(a[3]), "r"(b[0]), "r"(b[1]));
}

__device__ __forceinline__ void cp_async16(uint32_t smem_u32, const void* gptr) {
    asm volatile("cp.async.cg.shared.global [%0], [%1], 16;"
                 :: "r"(smem_u32), "l"(gptr));
}
#define CP_COMMIT() asm volatile("cp.async.commit_group;")
#define CP_WAIT2()  asm volatile("cp.async.wait_group 2;")

__device__ __forceinline__ float ex2f(float x) {
    float r; asm("ex2.approx.f32 %0, %1;" : "=f"(r) : "f"(x)); return r;
}
__device__ __forceinline__ float rcpf(float x) {
    float r; asm("rcp.approx.f32 %0, %1;" : "=f"(r) : "f"(x)); return r;
}
#define L2E 1.4426950408889634f
__device__ __forceinline__ float sigm_(float x) { return rcpf(1.0f + ex2f(-x * L2E)); }
__device__ __forceinline__ float tanh_(float x) { return 1.0f - 2.0f * rcpf(1.0f + ex2f(2.0f * L2E * x)); }

// ---------------- prep kernels ---------------------------------------------
__global__ void prep_w(const float* __restrict__ Wf, const float* __restrict__ Wb) {
    int i = blockIdx.x * 256 + threadIdx.x;
    if (i >= D_ * G4) return;
    int n = i % G4;
    int base = i - n;
    int src = base + ((n & 3) * H_ + (n >> 2));
    g_Wp[0][i] = f2tf32(Wf[src]);
    g_Wp[1][i] = f2tf32(Wb[src]);
}

__global__ void prep_u(const float* __restrict__ Uf, const float* __restrict__ Ub) {
    int i = blockIdx.x * 256 + threadIdx.x;
    if (i >= H_ * G4) return;
    int n = i % G4;
    int base = i - n;
    int src = base + ((n & 3) * H_ + (n >> 2));
    g_Up[0][i] = f2tf32(Uf[src]);
    g_Up[1][i] = f2tf32(Ub[src]);
}

__global__ void prep_state() {
    int i = blockIdx.x * 256 + threadIdx.x;
    if (i >= B_ * H_) return;
    g_h[0][0][i] = 0u; g_h[0][1][i] = 0u;
    g_h[1][0][i] = 0u; g_h[1][1][i] = 0u;
}

// ---------------- input projection GEMM (unchanged from R2) -----------------
__global__ __launch_bounds__(256) void proj_kernel(const float* __restrict__ x,
                                                   const float* __restrict__ bfv,
                                                   const float* __restrict__ bbv) {
    __shared__ uint32_t As[128][17];
    __shared__ uint32_t Bs[16][132];

    const int dir = blockIdx.z;
    const uint32_t* __restrict__ Wp = g_Wp[dir];
    const float* __restrict__ bias = dir ? bbv : bfv;
    const int row0 = blockIdx.x * 128;
    const int n0   = blockIdx.y * 128;
    const int tid  = threadIdx.x;
    const int lane = tid & 31;
    const int warp = tid >> 5;
    const int wm = warp & 1;
    const int wn = warp >> 1;

    float acc[4][4][4];
    #pragma unroll
    for (int mi = 0; mi < 4; mi++)
        #pragma unroll
        for (int ni = 0; ni < 4; ni++)
            #pragma unroll
            for (int e = 0; e < 4; e++) acc[mi][ni][e] = 0.0f;

    for (int k0 = 0; k0 < D_; k0 += 16) {
        {
            int r = tid >> 2;
            int c4 = (tid & 3) * 4;
            #pragma unroll
            for (int rr = 0; rr < 2; rr++) {
                int row = r + rr * 64;
                float4 v = *(const float4*)(x + (size_t)(row0 + row) * D_ + k0 + c4);
                As[row][c4 + 0] = f2tf32(v.x);
                As[row][c4 + 1] = f2tf32(v.y);
                As[row][c4 + 2] = f2tf32(v.z);
                As[row][c4 + 3] = f2tf32(v.w);
            }
        }
        {
            int r = tid >> 5;
            int c4 = (tid & 31) * 4;
            #pragma unroll
            for (int rr = 0; rr < 2; rr++) {
                int row = r + rr * 8;
                uint4 v = *(const uint4*)(Wp + (size_t)(k0 + row) * G4 + n0 + c4);
                Bs[row][c4 + 0] = v.x;
                Bs[row][c4 + 1] = v.y;
                Bs[row][c4 + 2] = v.z;
                Bs[row][c4 + 3] = v.w;
            }
        }
        __syncthreads();

        #pragma unroll
        for (int kk = 0; kk < 16; kk += 8) {
            uint32_t af[4][4];
            uint32_t bfr[4][2];
            #pragma unroll
            for (int mi = 0; mi < 4; mi++) {
                int rb = wm * 64 + mi * 16 + (lane >> 2);
                int cb = kk + (lane & 3);
                af[mi][0] = As[rb][cb];
                af[mi][1] = As[rb + 8][cb];
                af[mi][2] = As[rb][cb + 4];
                af[mi][3] = As[rb + 8][cb + 4];
            }
            #pragma unroll
            for (int ni = 0; ni < 4; ni++) {
                int nb = wn * 32 + ni * 8 + (lane >> 2);
                int kb = kk + (lane & 3);
                bfr[ni][0] = Bs[kb][nb];
                bfr[ni][1] = Bs[kb + 4][nb];
            }
            #pragma unroll
            for (int mi = 0; mi < 4; mi++)
                #pragma unroll
                for (int ni = 0; ni < 4; ni++)
                    mma_tf32(acc[mi][ni], af[mi], bfr[ni]);
        }
        __syncthreads();
    }

    #pragma unroll
    for (int mi = 0; mi < 4; mi++) {
        #pragma unroll
        for (int ni = 0; ni < 4; ni++) {
            int rl = wm * 64 + mi * 16 + (lane >> 2);
            int cl = wn * 32 + ni * 8 + 2 * (lane & 3);
            #pragma unroll
            for (int e = 0; e < 4; e++) {
                int rr = rl + (e >> 1) * 8;
                int cc = cl + (e & 1);
                int grow = row0 + rr;
                int b = grow >> 10;
                int t = grow & (T_ - 1);
                int n = n0 + cc;
                float v = acc[mi][ni][e] + __ldg(&bias[(n & 3) * H_ + (n >> 2)]);
                g_xz[dir][((size_t)t * B_ + b) * G4 + n] = v;
            }
        }
    }
}

// ---------------- persistent recurrent kernel -------------------------------
// grid (NBLK, 2). Block owns a 64-wide z tile (16 cells x 4 gates); U tile
// resident in smem; h streamed via 4-stage cp.async pipeline; c in registers;
// epilogue in mma-fragment layout with shfl gate exchange.
#define APAD 20
#define SMEM_U_WORDS (H_ * 64)
#define SMEM_A_WORDS (4 * 64 * APAD)
#define SMEM_BYTES   ((SMEM_U_WORDS + SMEM_A_WORDS) * 4)

__global__ __launch_bounds__(256, 1) void rnn_persistent(float* __restrict__ out) {
    extern __shared__ char smem_raw[];
    uint32_t* Us = (uint32_t*)smem_raw;                        // [H_][64] swizzled
    uint32_t (*As)[64][APAD] = (uint32_t (*)[64][APAD])(smem_raw + SMEM_U_WORDS * 4);

    const int dir = blockIdx.y;
    const int n0  = blockIdx.x * 64;
    const int tid = threadIdx.x;
    const int lane = tid & 31;
    const int warp = tid >> 5;
    const int wm = warp & 1;
    const int wn = warp >> 1;

    const uint32_t* __restrict__ Up = g_Up[dir];
    const float* __restrict__ xzd = g_xz[dir];

    // ---- load U tile into smem once (swizzle: col ^= (k&3)<<3) ----
    for (int i = tid; i < H_ * 16; i += 256) {
        int k  = i >> 4;
        int n4 = (i & 15) * 4;
        uint4 v = *(const uint4*)(Up + (size_t)k * G4 + n0 + n4);
        int sc = n4 ^ ((k & 3) << 3);
        *(uint4*)&Us[k * 64 + sc] = v;
    }
    __syncthreads();

    const int sw = (lane & 3) << 3;

    // per-thread cp.async source/dst geometry
    const int ar  = tid >> 2;                 // 0..63 (h row = batch)
    const int ac4 = (tid & 3) * 4;            // k sub-offset
    const uint32_t a_dst_base = (uint32_t)__cvta_generic_to_shared(&As[0][ar][ac4]);
    const uint32_t a_stage_stride = 64 * APAD * 4;

    // epilogue geometry (fragment layout)
    const int c0 = wn * 16 + 2 * (lane & 3);          // base z-col of this thread
    const int jl = wn * 4 + ((lane & 3) >> 1);        // local cell (ni adds 2*ni)
    const int jg = (n0 >> 2) + jl;                    // global cell col
    const bool store_lane = ((lane & 1) == 0);

    float creg[2][2][2];   // [mi][p][ni]
    #pragma unroll
    for (int mi = 0; mi < 2; mi++)
        #pragma unroll
        for (int p = 0; p < 2; p++)
            #pragma unroll
            for (int ni = 0; ni < 2; ni++) creg[mi][p][ni] = 0.0f;

    unsigned bar_gen_seen = g_bar_gen[dir];

    // xz prefetch for t = 0
    float2 xzr[2][2][2];   // [mi][p][ni]
    {
        const int tt0 = dir ? (T_ - 1) : 0;
        const float* xb = xzd + (size_t)tt0 * (B_ * G4) + n0 + c0;
        #pragma unroll
        for (int mi = 0; mi < 2; mi++)
            #pragma unroll
            for (int p = 0; p < 2; p++) {
                int b = wm * 32 + mi * 16 + (lane >> 2) + 8 * p;
                #pragma unroll
                for (int ni = 0; ni < 2; ni++)
                    xzr[mi][p][ni] = __ldcs((const float2*)(xb + (size_t)b * G4 + ni * 8));
            }
    }

    for (int t = 0; t < T_; t++) {
        const uint32_t* __restrict__ hp = g_h[dir][t & 1];
        uint32_t* __restrict__ hnext = g_h[dir][(t + 1) & 1];
        const int tt = dir ? (T_ - 1 - t) : t;

        float acc[2][2][4];
        #pragma unroll
        for (int mi = 0; mi < 2; mi++)
            #pragma unroll
            for (int ni = 0; ni < 2; ni++)
                #pragma unroll
                for (int e = 0; e < 4; e++) acc[mi][ni][e] = 0.0f;

        const char* hsrc = (const char*)(hp + (size_t)ar * H_ + ac4);

        // prologue: issue stages 0,1,2 (k0 = 0,16,32)
        #pragma unroll
        for (int s = 0; s < 3; s++) {
            cp_async16(a_dst_base + s * a_stage_stride, hsrc + (size_t)s * 64);
            CP_COMMIT();
        }

        for (int i = 0; i < 48; i++) {
            CP_WAIT2();
            __syncthreads();
            if (i < 45) {
                cp_async16(a_dst_base + ((i + 3) & 3) * a_stage_stride,
                           hsrc + (size_t)(i + 3) * 64);
            }
            CP_COMMIT();

            const int st = i & 3;
            const int k0 = i * 16;
            #pragma unroll
            for (int kk = 0; kk < 16; kk += 8) {
                uint32_t af[2][4];
                uint32_t bfr[2][2];
                #pragma unroll
                for (int mi = 0; mi < 2; mi++) {
                    int rb = wm * 32 + mi * 16 + (lane >> 2);
                    int cb = kk + (lane & 3);
                    af[mi][0] = As[st][rb][cb];
                    af[mi][1] = As[st][rb + 8][cb];
                    af[mi][2] = As[st][rb][cb + 4];
                    af[mi][3] = As[st][rb + 8][cb + 4];
                }
                #pragma unroll
                for (int ni = 0; ni < 2; ni++) {
                    int nb = wn * 16 + ni * 8 + (lane >> 2);
                    int kb = k0 + kk + (lane & 3);
                    bfr[ni][0] = Us[kb * 64 + (nb ^ sw)];
                    bfr[ni][1] = Us[(kb + 4) * 64 + (nb ^ sw)];
                }
                #pragma unroll
                for (int mi = 0; mi < 2; mi++)
                    #pragma unroll
                    for (int ni = 0; ni < 2; ni++)
                        mma_tf32(acc[mi][ni], af[mi], bfr[ni]);
            }
        }

        // ---- epilogue in fragment layout ----
        // thread holds z rows b(mi,p), cols c0 + ni*8 + q (gate pairs).
        // lanes l / l^1 hold complementary gate pairs of the same cells.
        #pragma unroll
        for (int mi = 0; mi < 2; mi++) {
            #pragma unroll
            for (int p = 0; p < 2; p++) {
                int b = wm * 32 + mi * 16 + (lane >> 2) + 8 * p;
                #pragma unroll
                for (int ni = 0; ni < 2; ni++) {
                    float a0 = acc[mi][ni][2 * p + 0] + xzr[mi][p][ni].x;
                    float a1 = acc[mi][ni][2 * p + 1] + xzr[mi][p][ni].y;
                    float b0 = __shfl_xor_sync(0xffffffffu, a0, 1);
                    float b1 = __shfl_xor_sync(0xffffffffu, a1, 1);
                    bool oddl = lane & 1;
                    float zi = oddl ? b0 : a0;
                    float zf = oddl ? b1 : a1;
                    float zg = oddl ? a0 : b0;
                    float zo = oddl ? a1 : b1;

                    float ig = sigm_(zi);
                    float fg = sigm_(zf);
                    float og = sigm_(zo);
                    float c = fg * creg[mi][p][ni] + ig * tanh_(zg);
                    creg[mi][p][ni] = c;
                    float h = og * tanh_(c);

                    if (store_lane) {
                        int j = jg + 2 * ni;
                        hnext[b * H_ + j] = f2tf32(h);
                        out[((size_t)b * T_ + tt) * OW + dir * H_ + j] = h;
                    }
                }
            }
        }

        // xz prefetch for t+1 (independent of barrier)
        if (t + 1 < T_) {
            const int tn = dir ? (T_ - 2 - t) : (t + 1);
            const float* xb = xzd + (size_t)tn * (B_ * G4) + n0 + c0;
            #pragma unroll
            for (int mi = 0; mi < 2; mi++)
                #pragma unroll
                for (int p = 0; p < 2; p++) {
                    int b = wm * 32 + mi * 16 + (lane >> 2) + 8 * p;
                    #pragma unroll
                    for (int ni = 0; ni < 2; ni++)
                        xzr[mi][p][ni] = __ldcs((const float2*)(xb + (size_t)b * G4 + ni * 8));
                }
        }

        // ---- per-direction grid barrier ----
        __syncthreads();
        if (tid == 0) {
            __threadfence();
            unsigned old = atomicAdd(&g_bar_cnt[dir], 1u);
            if (old == NBLK - 1) {
                g_bar_cnt[dir] = 0;
                __threadfence();
                atomicExch(&g_bar_gen[dir], bar_gen_seen + 1);
            } else {
                while (atomicAdd(&g_bar_gen[dir], 0u) == bar_gen_seen) { }
            }
        }
        bar_gen_seen++;
        __syncthreads();
    }
}

// ---------------- launch ----------------------------------------------------
extern "C" void kernel_launch(void* const* d_in, const int* in_sizes, int n_in,
                              void* d_out, int out_size) {
    (void)in_sizes; (void)n_in; (void)out_size;
    const float* x  = (const float*)d_in[0];
    const float* Wf = (const float*)d_in[1];
    const float* Uf = (const float*)d_in[2];
    const float* bf = (const float*)d_in[3];
    const float* Wb = (const float*)d_in[4];
    const float* Ub = (const float*)d_in[5];
    const float* bb = (const float*)d_in[6];
    float* out = (float*)d_out;

    cudaFuncSetAttribute(rnn_persistent,
                         cudaFuncAttributeMaxDynamicSharedMemorySize, SMEM_BYTES);

    prep_w<<<(D_ * G4 + 255) / 256, 256>>>(Wf, Wb);
    prep_u<<<(H_ * G4 + 255) / 256, 256>>>(Uf, Ub);
    prep_state<<<(B_ * H_ + 255) / 256, 256>>>();

    proj_kernel<<<dim3(512, 24, 2), 256>>>(x, bf, bb);

    rnn_persistent<<<dim3(NBLK, 2), 256, SMEM_BYTES>>>(out);
}

// round 4
// speedup vs baseline: 2.4796x; 1.2846x over previous
#include <cuda_runtime.h>
#include <cuda_fp16.h>
#include <cstdint>
#include <cmath>

#define B_ 64
#define T_ 1024
#define D_ 512
#define H_ 768
#define G4 3072   // 4*H
#define OW 1536   // 2*H
#define NBLK 48   // column blocks per direction

// ---------------- scratch (device globals) ----------------------------------
__device__ float    g_xz[2][(size_t)T_ * B_ * G4];   // gate-permuted input projections, fp32
__device__ uint32_t g_Wp[2][D_ * G4];                // permuted W, tf32 bits (proj)
__device__ __half   g_Ut[2][(size_t)G4 * H_];        // permuted U, TRANSPOSED [n][k], fp16
__device__ __half   g_h[2][2][B_ * H_];              // [dir][phase], fp16
__device__ unsigned g_bar_cnt[2];
__device__ unsigned g_bar_gen[2];

// ---------------- helpers --------------------------------------------------
__device__ __forceinline__ uint32_t f2tf32(float f) {
    uint32_t r;
    asm("cvt.rna.tf32.f32 %0, %1;" : "=r"(r) : "f"(f));
    return r;
}

__device__ __forceinline__ void mma_tf32(float* c, const uint32_t* a, const uint32_t* b) {
    asm volatile(
        "mma.sync.aligned.m16n8k8.row.col.f32.tf32.tf32.f32 "
        "{%0,%1,%2,%3}, {%4,%5,%6,%7}, {%8,%9}, {%0,%1,%2,%3};"
        : "+f"(c[0]), "+f"(c[1]), "+f"(c[2]), "+f"(c[3])
        : "r"(a[0]), "r"(a[1]), "r"(a[2]), "r"(a[3]), "r"(b[0]), "r"(b[1]));
}

__device__ __forceinline__ void mma_f16(float* c, const uint32_t* a, const uint32_t* b) {
    asm volatile(
        "mma.sync.aligned.m16n8k16.row.col.f32.f16.f16.f32 "
        "{%0,%1,%2,%3}, {%4,%5,%6,%7}, {%8,%9}, {%0,%1,%2,%3};"
        : "+f"(c[0]), "+f"(c[1]), "+f"(c[2]), "+f"(c[3])
        : "r"(a[0]), "r"(a[1]), "r"(a[2]), "r"(a[3]), "r"(b[0]), "r"(b[1]));
}

__device__ __forceinline__ void cp_async16(uint32_t smem_u32, const void* gptr) {
    asm volatile("cp.async.cg.shared.global [%0], [%1], 16;"
                 :: "r"(smem_u32), "l"(gptr));
}
#define CP_COMMIT() asm volatile("cp.async.commit_group;")
#define CP_WAIT2()  asm volatile("cp.async.wait_group 2;")

__device__ __forceinline__ float ex2f(float x) {
    float r; asm("ex2.approx.f32 %0, %1;" : "=f"(r) : "f"(x)); return r;
}
__device__ __forceinline__ float rcpf(float x) {
    float r; asm("rcp.approx.f32 %0, %1;" : "=f"(r) : "f"(x)); return r;
}
#define L2E 1.4426950408889634f
__device__ __forceinline__ float sigm_(float x) { return rcpf(1.0f + ex2f(-x * L2E)); }
__device__ __forceinline__ float tanh_(float x) { return 1.0f - 2.0f * rcpf(1.0f + ex2f(2.0f * L2E * x)); }

// ---------------- prep kernels ---------------------------------------------
__global__ void prep_w(const float* __restrict__ Wf, const float* __restrict__ Wb) {
    int i = blockIdx.x * 256 + threadIdx.x;
    if (i >= D_ * G4) return;
    int n = i % G4;
    int base = i - n;
    int src = base + ((n & 3) * H_ + (n >> 2));
    g_Wp[0][i] = f2tf32(Wf[src]);
    g_Wp[1][i] = f2tf32(Wb[src]);
}

// U: permuted col n = 4j+g <- src col g*H + j ; store TRANSPOSED [n][k], fp16.
__global__ void prep_u(const float* __restrict__ Uf, const float* __restrict__ Ub) {
    int i = blockIdx.x * 256 + threadIdx.x;
    if (i >= H_ * G4) return;
    int n = i % G4;
    int k = i / G4;
    int src = k * G4 + (n & 3) * H_ + (n >> 2);
    g_Ut[0][(size_t)n * H_ + k] = __float2half(Uf[src]);
    g_Ut[1][(size_t)n * H_ + k] = __float2half(Ub[src]);
}

__global__ void prep_state() {
    int i = blockIdx.x * 256 + threadIdx.x;
    if (i >= B_ * H_) return;
    g_h[0][0][i] = __half(0.0f); g_h[0][1][i] = __half(0.0f);
    g_h[1][0][i] = __half(0.0f); g_h[1][1][i] = __half(0.0f);
}

// ---------------- input projection GEMM (tf32, unchanged) -------------------
__global__ __launch_bounds__(256) void proj_kernel(const float* __restrict__ x,
                                                   const float* __restrict__ bfv,
                                                   const float* __restrict__ bbv) {
    __shared__ uint32_t As[128][17];
    __shared__ uint32_t Bs[16][132];

    const int dir = blockIdx.z;
    const uint32_t* __restrict__ Wp = g_Wp[dir];
    const float* __restrict__ bias = dir ? bbv : bfv;
    const int row0 = blockIdx.x * 128;
    const int n0   = blockIdx.y * 128;
    const int tid  = threadIdx.x;
    const int lane = tid & 31;
    const int warp = tid >> 5;
    const int wm = warp & 1;
    const int wn = warp >> 1;

    float acc[4][4][4];
    #pragma unroll
    for (int mi = 0; mi < 4; mi++)
        #pragma unroll
        for (int ni = 0; ni < 4; ni++)
            #pragma unroll
            for (int e = 0; e < 4; e++) acc[mi][ni][e] = 0.0f;

    for (int k0 = 0; k0 < D_; k0 += 16) {
        {
            int r = tid >> 2;
            int c4 = (tid & 3) * 4;
            #pragma unroll
            for (int rr = 0; rr < 2; rr++) {
                int row = r + rr * 64;
                float4 v = *(const float4*)(x + (size_t)(row0 + row) * D_ + k0 + c4);
                As[row][c4 + 0] = f2tf32(v.x);
                As[row][c4 + 1] = f2tf32(v.y);
                As[row][c4 + 2] = f2tf32(v.z);
                As[row][c4 + 3] = f2tf32(v.w);
            }
        }
        {
            int r = tid >> 5;
            int c4 = (tid & 31) * 4;
            #pragma unroll
            for (int rr = 0; rr < 2; rr++) {
                int row = r + rr * 8;
                uint4 v = *(const uint4*)(Wp + (size_t)(k0 + row) * G4 + n0 + c4);
                Bs[row][c4 + 0] = v.x;
                Bs[row][c4 + 1] = v.y;
                Bs[row][c4 + 2] = v.z;
                Bs[row][c4 + 3] = v.w;
            }
        }
        __syncthreads();

        #pragma unroll
        for (int kk = 0; kk < 16; kk += 8) {
            uint32_t af[4][4];
            uint32_t bfr[4][2];
            #pragma unroll
            for (int mi = 0; mi < 4; mi++) {
                int rb = wm * 64 + mi * 16 + (lane >> 2);
                int cb = kk + (lane & 3);
                af[mi][0] = As[rb][cb];
                af[mi][1] = As[rb + 8][cb];
                af[mi][2] = As[rb][cb + 4];
                af[mi][3] = As[rb + 8][cb + 4];
            }
            #pragma unroll
            for (int ni = 0; ni < 4; ni++) {
                int nb = wn * 32 + ni * 8 + (lane >> 2);
                int kb = kk + (lane & 3);
                bfr[ni][0] = Bs[kb][nb];
                bfr[ni][1] = Bs[kb + 4][nb];
            }
            #pragma unroll
            for (int mi = 0; mi < 4; mi++)
                #pragma unroll
                for (int ni = 0; ni < 4; ni++)
                    mma_tf32(acc[mi][ni], af[mi], bfr[ni]);
        }
        __syncthreads();
    }

    #pragma unroll
    for (int mi = 0; mi < 4; mi++) {
        #pragma unroll
        for (int ni = 0; ni < 4; ni++) {
            int rl = wm * 64 + mi * 16 + (lane >> 2);
            int cl = wn * 32 + ni * 8 + 2 * (lane & 3);
            #pragma unroll
            for (int e = 0; e < 4; e++) {
                int rr = rl + (e >> 1) * 8;
                int cc = cl + (e & 1);
                int grow = row0 + rr;
                int b = grow >> 10;
                int t = grow & (T_ - 1);
                int n = n0 + cc;
                float v = acc[mi][ni][e] + __ldg(&bias[(n & 3) * H_ + (n >> 2)]);
                g_xz[dir][((size_t)t * B_ + b) * G4 + n] = v;
            }
        }
    }
}

// ---------------- persistent recurrent kernel (fp16 mma) --------------------
// U^T tile [64 n][768 k] fp16 in smem; h fp16 streamed via 4-stage cp.async
// (stages of 64x32 halves); epilogue in fragment layout, c in registers.
#define UT_PAD   776                 // halves per Ut row (388 words: conflict-free)
#define A_PAD    40                  // halves per As row (20 words)
#define SMEM_UT_HALVES (64 * UT_PAD)
#define SMEM_A_HALVES  (4 * 64 * A_PAD)
#define SMEM_BYTES ((SMEM_UT_HALVES + SMEM_A_HALVES) * 2)

__global__ __launch_bounds__(256, 1) void rnn_persistent(float* __restrict__ out) {
    extern __shared__ char smem_raw[];
    __half* Us = (__half*)smem_raw;                              // [64][UT_PAD]
    __half* Ah = (__half*)(smem_raw + SMEM_UT_HALVES * 2);       // 4 stages [64][A_PAD]
    const uint32_t* UsW = (const uint32_t*)Us;                   // row stride 388 words
    const uint32_t* AhW = (const uint32_t*)Ah;                   // row stride 20 words

    const int dir = blockIdx.y;
    const int n0  = blockIdx.x * 64;
    const int tid = threadIdx.x;
    const int lane = tid & 31;
    const int warp = tid >> 5;
    const int wm = warp & 1;
    const int wn = warp >> 1;

    const float* __restrict__ xzd = g_xz[dir];

    // ---- load U^T tile into smem once (rows n0..n0+63, k-contiguous) ----
    {
        const __half* src = g_Ut[dir] + (size_t)n0 * H_;
        for (int idx = tid; idx < 64 * 96; idx += 256) {   // 96 uint4 per row
            int n = idx / 96, ch = idx % 96;
            uint4 v = *(const uint4*)(src + (size_t)n * H_ + ch * 8);
            *(uint4*)(Us + n * UT_PAD + ch * 8) = v;
        }
    }
    __syncthreads();

    // cp.async geometry: stage = 64 rows x 32 halves; 4 threads per row, 16B each
    const int ar  = tid >> 2;
    const int ac8 = (tid & 3) * 8;            // halves offset within stage row
    const uint32_t a_dst_base =
        (uint32_t)__cvta_generic_to_shared(Ah + ar * A_PAD + ac8);
    const uint32_t a_stage_stride = 64 * A_PAD * 2;  // bytes

    // epilogue geometry (fragment layout, same as R3)
    const int c0 = wn * 16 + 2 * (lane & 3);
    const int jl = wn * 4 + ((lane & 3) >> 1);
    const int jg = (n0 >> 2) + jl;
    const bool store_lane = ((lane & 1) == 0);

    float creg[2][2][2];
    #pragma unroll
    for (int mi = 0; mi < 2; mi++)
        #pragma unroll
        for (int p = 0; p < 2; p++)
            #pragma unroll
            for (int ni = 0; ni < 2; ni++) creg[mi][p][ni] = 0.0f;

    unsigned bar_gen_seen = g_bar_gen[dir];

    float2 xzr[2][2][2];
    {
        const int tt0 = dir ? (T_ - 1) : 0;
        const float* xb = xzd + (size_t)tt0 * (B_ * G4) + n0 + c0;
        #pragma unroll
        for (int mi = 0; mi < 2; mi++)
            #pragma unroll
            for (int p = 0; p < 2; p++) {
                int b = wm * 32 + mi * 16 + (lane >> 2) + 8 * p;
                #pragma unroll
                for (int ni = 0; ni < 2; ni++)
                    xzr[mi][p][ni] = __ldcs((const float2*)(xb + (size_t)b * G4 + ni * 8));
            }
    }

    for (int t = 0; t < T_; t++) {
        const __half* __restrict__ hp = g_h[dir][t & 1];
        __half* __restrict__ hnext = g_h[dir][(t + 1) & 1];
        const int tt = dir ? (T_ - 1 - t) : t;

        float acc[2][2][4];
        #pragma unroll
        for (int mi = 0; mi < 2; mi++)
            #pragma unroll
            for (int ni = 0; ni < 2; ni++)
                #pragma unroll
                for (int e = 0; e < 4; e++) acc[mi][ni][e] = 0.0f;

        const char* hsrc = (const char*)(hp + (size_t)ar * H_ + ac8);

        // prologue: stages 0,1,2 (k = 0,32,64)
        #pragma unroll
        for (int s = 0; s < 3; s++) {
            cp_async16(a_dst_base + s * a_stage_stride, hsrc + (size_t)s * 64);
            CP_COMMIT();
        }

        for (int i = 0; i < 24; i++) {     // k32 stages
            CP_WAIT2();
            __syncthreads();
            if (i < 21)
                cp_async16(a_dst_base + ((i + 3) & 3) * a_stage_stride,
                           hsrc + (size_t)(i + 3) * 64);
            CP_COMMIT();

            const int stw = (i & 3) * 64 * 20;   // stage base, words
            #pragma unroll
            for (int kk = 0; kk < 2; kk++) {     // two k16 slices
                uint32_t af[2][4];
                uint32_t bfr[2][2];
                #pragma unroll
                for (int mi = 0; mi < 2; mi++) {
                    int rb = wm * 32 + mi * 16 + (lane >> 2);
                    int kw = kk * 8 + (lane & 3);
                    af[mi][0] = AhW[stw + rb * 20 + kw];
                    af[mi][1] = AhW[stw + (rb + 8) * 20 + kw];
                    af[mi][2] = AhW[stw + rb * 20 + kw + 4];
                    af[mi][3] = AhW[stw + (rb + 8) * 20 + kw + 4];
                }
                #pragma unroll
                for (int ni = 0; ni < 2; ni++) {
                    int nb = wn * 16 + ni * 8 + (lane >> 2);
                    int kw = i * 16 + kk * 8 + (lane & 3);
                    bfr[ni][0] = UsW[nb * 388 + kw];
                    bfr[ni][1] = UsW[nb * 388 + kw + 4];
                }
                #pragma unroll
                for (int mi = 0; mi < 2; mi++)
                    #pragma unroll
                    for (int ni = 0; ni < 2; ni++)
                        mma_f16(acc[mi][ni], af[mi], bfr[ni]);
            }
        }

        // ---- epilogue in fragment layout ----
        #pragma unroll
        for (int mi = 0; mi < 2; mi++) {
            #pragma unroll
            for (int p = 0; p < 2; p++) {
                int b = wm * 32 + mi * 16 + (lane >> 2) + 8 * p;
                #pragma unroll
                for (int ni = 0; ni < 2; ni++) {
                    float a0 = acc[mi][ni][2 * p + 0] + xzr[mi][p][ni].x;
                    float a1 = acc[mi][ni][2 * p + 1] + xzr[mi][p][ni].y;
                    float b0 = __shfl_xor_sync(0xffffffffu, a0, 1);
                    float b1 = __shfl_xor_sync(0xffffffffu, a1, 1);
                    bool oddl = lane & 1;
                    float zi = oddl ? b0 : a0;
                    float zf = oddl ? b1 : a1;
                    float zg = oddl ? a0 : b0;
                    float zo = oddl ? a1 : b1;

                    float ig = sigm_(zi);
                    float fg = sigm_(zf);
                    float og = sigm_(zo);
                    float c = fg * creg[mi][p][ni] + ig * tanh_(zg);
                    creg[mi][p][ni] = c;
                    float h = og * tanh_(c);

                    if (store_lane) {
                        int j = jg + 2 * ni;
                        hnext[b * H_ + j] = __float2half(h);
                        out[((size_t)b * T_ + tt) * OW + dir * H_ + j] = h;
                    }
                }
            }
        }

        // xz prefetch for t+1
        if (t + 1 < T_) {
            const int tn = dir ? (T_ - 2 - t) : (t + 1);
            const float* xb = xzd + (size_t)tn * (B_ * G4) + n0 + c0;
            #pragma unroll
            for (int mi = 0; mi < 2; mi++)
                #pragma unroll
                for (int p = 0; p < 2; p++) {
                    int b = wm * 32 + mi * 16 + (lane >> 2) + 8 * p;
                    #pragma unroll
                    for (int ni = 0; ni < 2; ni++)
                        xzr[mi][p][ni] = __ldcs((const float2*)(xb + (size_t)b * G4 + ni * 8));
                }
        }

        // ---- per-direction grid barrier (volatile poll, atomic arrive) ----
        __syncthreads();
        if (tid == 0) {
            __threadfence();
            unsigned old = atomicAdd(&g_bar_cnt[dir], 1u);
            if (old == NBLK - 1) {
                g_bar_cnt[dir] = 0;
                __threadfence();
                atomicExch(&g_bar_gen[dir], bar_gen_seen + 1);
            } else {
                volatile unsigned* gen = (volatile unsigned*)&g_bar_gen[dir];
                while (*gen == bar_gen_seen) { }
                __threadfence();
            }
        }
        bar_gen_seen++;
        __syncthreads();
    }
}

// ---------------- launch ----------------------------------------------------
extern "C" void kernel_launch(void* const* d_in, const int* in_sizes, int n_in,
                              void* d_out, int out_size) {
    (void)in_sizes; (void)n_in; (void)out_size;
    const float* x  = (const float*)d_in[0];
    const float* Wf = (const float*)d_in[1];
    const float* Uf = (const float*)d_in[2];
    const float* bf = (const float*)d_in[3];
    const float* Wb = (const float*)d_in[4];
    const float* Ub = (const float*)d_in[5];
    const float* bb = (const float*)d_in[6];
    float* out = (float*)d_out;

    cudaFuncSetAttribute(rnn_persistent,
                         cudaFuncAttributeMaxDynamicSharedMemorySize, SMEM_BYTES);

    prep_w<<<(D_ * G4 + 255) / 256, 256>>>(Wf, Wb);
    prep_u<<<(H_ * G4 + 255) / 256, 256>>>(Uf, Ub);
    prep_state<<<(B_ * H_ + 255) / 256, 256>>>();

    proj_kernel<<<dim3(512, 24, 2), 256>>>(x, bf, bb);

    rnn_persistent<<<dim3(NBLK, 2), 256, SMEM_BYTES>>>(out);
}

// round 5
// speedup vs baseline: 3.0915x; 1.2468x over previous
#include <cuda_runtime.h>
#include <cuda_fp16.h>
#include <cstdint>
#include <cmath>

#define B_ 64
#define T_ 1024
#define D_ 512
#define H_ 768
#define G4 3072   // 4*H
#define OW 1536   // 2*H
#define NBLK 48   // column blocks per direction

// ---------------- scratch (device globals) ----------------------------------
__device__ float    g_xz[2][(size_t)T_ * B_ * G4];   // gate-permuted input projections, fp32
__device__ __half   g_Wph[2][(size_t)G4 * D_];       // permuted W, TRANSPOSED [n][k], fp16
__device__ __half   g_Ut[2][(size_t)G4 * H_];        // permuted U, TRANSPOSED [n][k], fp16
__device__ __half   g_h[2][2][B_ * H_];              // [dir][phase], fp16
__device__ unsigned g_bar_cnt[2];
__device__ unsigned g_bar_gen[2];

// ---------------- helpers --------------------------------------------------
__device__ __forceinline__ void mma_f16(float* c, const uint32_t* a,
                                        uint32_t b0, uint32_t b1) {
    asm volatile(
        "mma.sync.aligned.m16n8k16.row.col.f32.f16.f16.f32 "
        "{%0,%1,%2,%3}, {%4,%5,%6,%7}, {%8,%9}, {%0,%1,%2,%3};"
        : "+f"(c[0]), "+f"(c[1]), "+f"(c[2]), "+f"(c[3])
        : "r"(a[0]), "r"(a[1]), "r"(a[2]), "r"(a[3]), "r"(b0), "r"(b1));
}

__device__ __forceinline__ void ldsm_x4(uint32_t* r, uint32_t saddr) {
    asm volatile("ldmatrix.sync.aligned.m8n8.x4.shared.b16 {%0,%1,%2,%3}, [%4];"
        : "=r"(r[0]), "=r"(r[1]), "=r"(r[2]), "=r"(r[3]) : "r"(saddr));
}

__device__ __forceinline__ void cp_async16(uint32_t smem_u32, const void* gptr) {
    asm volatile("cp.async.cg.shared.global [%0], [%1], 16;"
                 :: "r"(smem_u32), "l"(gptr));
}
#define CP_COMMIT() asm volatile("cp.async.commit_group;")
#define CP_WAIT2()  asm volatile("cp.async.wait_group 2;")

__device__ __forceinline__ float ex2f(float x) {
    float r; asm("ex2.approx.f32 %0, %1;" : "=f"(r) : "f"(x)); return r;
}
__device__ __forceinline__ float rcpf(float x) {
    float r; asm("rcp.approx.f32 %0, %1;" : "=f"(r) : "f"(x)); return r;
}
#define L2E 1.4426950408889634f
__device__ __forceinline__ float sigm_(float x) { return rcpf(1.0f + ex2f(-x * L2E)); }
__device__ __forceinline__ float tanh_(float x) { return 1.0f - 2.0f * rcpf(1.0f + ex2f(2.0f * L2E * x)); }

// ---------------- prep kernels ---------------------------------------------
// W: permuted col n = 4j+g <- src col g*H + j ; store TRANSPOSED [n][k], fp16.
__global__ void prep_w(const float* __restrict__ Wf, const float* __restrict__ Wb) {
    int i = blockIdx.x * 256 + threadIdx.x;
    if (i >= G4 * D_) return;
    int n = i / D_;
    int k = i % D_;
    int src = k * G4 + (n & 3) * H_ + (n >> 2);
    g_Wph[0][i] = __float2half(Wf[src]);
    g_Wph[1][i] = __float2half(Wb[src]);
}

__global__ void prep_u(const float* __restrict__ Uf, const float* __restrict__ Ub) {
    int i = blockIdx.x * 256 + threadIdx.x;
    if (i >= H_ * G4) return;
    int n = i % G4;
    int k = i / G4;
    int src = k * G4 + (n & 3) * H_ + (n >> 2);
    g_Ut[0][(size_t)n * H_ + k] = __float2half(Uf[src]);
    g_Ut[1][(size_t)n * H_ + k] = __float2half(Ub[src]);
}

__global__ void prep_state() {
    int i = blockIdx.x * 256 + threadIdx.x;
    if (i >= B_ * H_) return;
    g_h[0][0][i] = __half(0.0f); g_h[0][1][i] = __half(0.0f);
    g_h[1][0][i] = __half(0.0f); g_h[1][1][i] = __half(0.0f);
}

// ---------------- input projection GEMM (fp16 mma + ldmatrix) ---------------
// A = x [M=B*T, K=D] fp32->fp16; B = g_Wph [n][k] fp16. BM=128, BN=128, BK=16.
#define PJ_PAD 24   // halves per smem row (48B stride, LDSM conflict-free)

__global__ __launch_bounds__(256) void proj_kernel(const float* __restrict__ x,
                                                   const float* __restrict__ bfv,
                                                   const float* __restrict__ bbv) {
    __shared__ __half As[128][PJ_PAD];
    __shared__ __half Bs[128][PJ_PAD];

    const int dir = blockIdx.z;
    const __half* __restrict__ Wp = g_Wph[dir];
    const float* __restrict__ bias = dir ? bbv : bfv;
    const int row0 = blockIdx.x * 128;
    const int n0   = blockIdx.y * 128;
    const int tid  = threadIdx.x;
    const int lane = tid & 31;
    const int warp = tid >> 5;
    const int wm = warp & 1;
    const int wn = warp >> 1;

    const uint32_t As_base = (uint32_t)__cvta_generic_to_shared(&As[0][0]);
    const uint32_t Bs_base = (uint32_t)__cvta_generic_to_shared(&Bs[0][0]);
    const int lrow = lane & 15;
    const int lkc  = (lane >> 4) * 8;      // k chunk for ldmatrix

    float acc[4][4][4];
    #pragma unroll
    for (int mi = 0; mi < 4; mi++)
        #pragma unroll
        for (int ni = 0; ni < 4; ni++)
            #pragma unroll
            for (int e = 0; e < 4; e++) acc[mi][ni][e] = 0.0f;

    for (int k0 = 0; k0 < D_; k0 += 16) {
        {   // A: 128 rows x 16 halves (convert fp32 -> fp16)
            int r = tid >> 2;
            int c4 = (tid & 3) * 4;
            #pragma unroll
            for (int rr = 0; rr < 2; rr++) {
                int row = r + rr * 64;
                float4 v = *(const float4*)(x + (size_t)(row0 + row) * D_ + k0 + c4);
                __half2* dst = (__half2*)&As[row][c4];
                dst[0] = __floats2half2_rn(v.x, v.y);
                dst[1] = __floats2half2_rn(v.z, v.w);
            }
        }
        {   // B: 128 n-rows x 16 halves from [n][k] global
            int row = tid >> 1;
            int c8 = (tid & 1) * 8;
            uint4 v = *(const uint4*)(Wp + (size_t)(n0 + row) * D_ + k0 + c8);
            *(uint4*)&Bs[row][c8] = v;
        }
        __syncthreads();

        uint32_t bfr[4][2];
        #pragma unroll
        for (int np = 0; np < 2; np++) {
            uint32_t b4[4];
            ldsm_x4(b4, Bs_base + (uint32_t)(((wn * 32 + np * 16 + lrow) * PJ_PAD + lkc) * 2));
            bfr[np * 2 + 0][0] = b4[0]; bfr[np * 2 + 1][0] = b4[1];
            bfr[np * 2 + 0][1] = b4[2]; bfr[np * 2 + 1][1] = b4[3];
        }
        #pragma unroll
        for (int mi = 0; mi < 4; mi++) {
            uint32_t af[4];
            ldsm_x4(af, As_base + (uint32_t)(((wm * 64 + mi * 16 + lrow) * PJ_PAD + lkc) * 2));
            #pragma unroll
            for (int ni = 0; ni < 4; ni++)
                mma_f16(acc[mi][ni], af, bfr[ni][0], bfr[ni][1]);
        }
        __syncthreads();
    }

    #pragma unroll
    for (int mi = 0; mi < 4; mi++) {
        #pragma unroll
        for (int ni = 0; ni < 4; ni++) {
            int rl = wm * 64 + mi * 16 + (lane >> 2);
            int cl = wn * 32 + ni * 8 + 2 * (lane & 3);
            #pragma unroll
            for (int e = 0; e < 4; e++) {
                int rr = rl + (e >> 1) * 8;
                int cc = cl + (e & 1);
                int grow = row0 + rr;
                int b = grow >> 10;
                int t = grow & (T_ - 1);
                int n = n0 + cc;
                float v = acc[mi][ni][e] + __ldg(&bias[(n & 3) * H_ + (n >> 2)]);
                g_xz[dir][((size_t)t * B_ + b) * G4 + n] = v;
            }
        }
    }
}

// ---------------- persistent recurrent kernel (fp16 mma + ldmatrix) ---------
// U^T tile [64 n][768 k] fp16 in smem; h fp16 streamed via 4-stage cp.async
// (stages of 64 x 64 halves); all fragments via ldmatrix.x4.
#define UT_PAD   776                 // halves per Ut row
#define A_PAD    72                  // halves per A-stage row (144B stride)
#define SMEM_UT_HALVES (64 * UT_PAD)
#define SMEM_A_HALVES  (4 * 64 * A_PAD)
#define SMEM_BYTES ((SMEM_UT_HALVES + SMEM_A_HALVES) * 2)

__global__ __launch_bounds__(256, 1) void rnn_persistent(float* __restrict__ out) {
    extern __shared__ char smem_raw[];
    __half* Us = (__half*)smem_raw;                              // [64][UT_PAD]
    __half* Ah = (__half*)(smem_raw + SMEM_UT_HALVES * 2);       // 4 stages [64][A_PAD]

    const int dir = blockIdx.y;
    const int n0  = blockIdx.x * 64;
    const int tid = threadIdx.x;
    const int lane = tid & 31;
    const int warp = tid >> 5;
    const int wm = warp & 1;
    const int wn = warp >> 1;

    const float* __restrict__ xzd = g_xz[dir];

    // ---- load U^T tile into smem once ----
    {
        const __half* src = g_Ut[dir] + (size_t)n0 * H_;
        for (int idx = tid; idx < 64 * 96; idx += 256) {   // 96 uint4 per row
            int n = idx / 96, ch = idx % 96;
            uint4 v = *(const uint4*)(src + (size_t)n * H_ + ch * 8);
            *(uint4*)(Us + n * UT_PAD + ch * 8) = v;
        }
    }
    __syncthreads();

    // cp.async geometry: stage = 64 rows x 64 halves (128B/row), 4 thr/row x 32B
    const int ar   = tid >> 2;
    const int ac16 = (tid & 3) * 16;          // halves offset within stage row
    const uint32_t a_dst_base =
        (uint32_t)__cvta_generic_to_shared(Ah + ar * A_PAD + ac16);
    const uint32_t a_stage_stride = 64 * A_PAD * 2;  // bytes

    // ldmatrix geometry
    const int lrow = lane & 15;
    const int lkc  = (lane >> 4) * 8;
    const uint32_t Ah_base = (uint32_t)__cvta_generic_to_shared(Ah);
    const uint32_t a_frag0 = Ah_base + (uint32_t)(((wm * 32 + lrow) * A_PAD + lkc) * 2);
    const uint32_t u_frag0 = (uint32_t)__cvta_generic_to_shared(Us)
                           + (uint32_t)(((wn * 16 + lrow) * UT_PAD + lkc) * 2);

    // epilogue geometry (fragment layout)
    const int c0 = wn * 16 + 2 * (lane & 3);
    const int jl = wn * 4 + ((lane & 3) >> 1);
    const int jg = (n0 >> 2) + jl;
    const bool store_lane = ((lane & 1) == 0);

    float creg[2][2][2];
    #pragma unroll
    for (int mi = 0; mi < 2; mi++)
        #pragma unroll
        for (int p = 0; p < 2; p++)
            #pragma unroll
            for (int ni = 0; ni < 2; ni++) creg[mi][p][ni] = 0.0f;

    unsigned bar_gen_seen = g_bar_gen[dir];

    float2 xzr[2][2][2];
    {
        const int tt0 = dir ? (T_ - 1) : 0;
        const float* xb = xzd + (size_t)tt0 * (B_ * G4) + n0 + c0;
        #pragma unroll
        for (int mi = 0; mi < 2; mi++)
            #pragma unroll
            for (int p = 0; p < 2; p++) {
                int b = wm * 32 + mi * 16 + (lane >> 2) + 8 * p;
                #pragma unroll
                for (int ni = 0; ni < 2; ni++)
                    xzr[mi][p][ni] = __ldcs((const float2*)(xb + (size_t)b * G4 + ni * 8));
            }
    }

    for (int t = 0; t < T_; t++) {
        const __half* __restrict__ hp = g_h[dir][t & 1];
        __half* __restrict__ hnext = g_h[dir][(t + 1) & 1];
        const int tt = dir ? (T_ - 1 - t) : t;

        float acc[2][2][4];
        #pragma unroll
        for (int mi = 0; mi < 2; mi++)
            #pragma unroll
            for (int ni = 0; ni < 2; ni++)
                #pragma unroll
                for (int e = 0; e < 4; e++) acc[mi][ni][e] = 0.0f;

        const char* hsrc = (const char*)(hp + (size_t)ar * H_ + ac16);

        // prologue: stages 0,1,2 (k = 0,64,128)
        #pragma unroll
        for (int s = 0; s < 3; s++) {
            cp_async16(a_dst_base + s * a_stage_stride, hsrc + (size_t)s * 128);
            cp_async16(a_dst_base + s * a_stage_stride + 16, hsrc + (size_t)s * 128 + 16);
            CP_COMMIT();
        }

        for (int i = 0; i < 12; i++) {     // k64 stages
            CP_WAIT2();
            __syncthreads();
            if (i < 9) {
                uint32_t d = a_dst_base + ((i + 3) & 3) * a_stage_stride;
                const char* s = hsrc + (size_t)(i + 3) * 128;
                cp_async16(d, s);
                cp_async16(d + 16, s + 16);
            }
            CP_COMMIT();

            const uint32_t a_st = a_frag0 + (uint32_t)(i & 3) * a_stage_stride;
            const uint32_t u_st = u_frag0 + (uint32_t)(i * 128);   // i*64 halves
            #pragma unroll
            for (int ks = 0; ks < 4; ks++) {
                uint32_t b4[4];
                ldsm_x4(b4, u_st + ks * 32);
                uint32_t af0[4], af1[4];
                ldsm_x4(af0, a_st + ks * 32);
                ldsm_x4(af1, a_st + ks * 32 + 16 * A_PAD * 2);
                mma_f16(acc[0][0], af0, b4[0], b4[2]);
                mma_f16(acc[0][1], af0, b4[1], b4[3]);
                mma_f16(acc[1][0], af1, b4[0], b4[2]);
                mma_f16(acc[1][1], af1, b4[1], b4[3]);
            }
        }

        // ---- epilogue in fragment layout ----
        #pragma unroll
        for (int mi = 0; mi < 2; mi++) {
            #pragma unroll
            for (int p = 0; p < 2; p++) {
                int b = wm * 32 + mi * 16 + (lane >> 2) + 8 * p;
                #pragma unroll
                for (int ni = 0; ni < 2; ni++) {
                    float a0 = acc[mi][ni][2 * p + 0] + xzr[mi][p][ni].x;
                    float a1 = acc[mi][ni][2 * p + 1] + xzr[mi][p][ni].y;
                    float b0 = __shfl_xor_sync(0xffffffffu, a0, 1);
                    float b1 = __shfl_xor_sync(0xffffffffu, a1, 1);
                    bool oddl = lane & 1;
                    float zi = oddl ? b0 : a0;
                    float zf = oddl ? b1 : a1;
                    float zg = oddl ? a0 : b0;
                    float zo = oddl ? a1 : b1;

                    float ig = sigm_(zi);
                    float fg = sigm_(zf);
                    float og = sigm_(zo);
                    float c = fg * creg[mi][p][ni] + ig * tanh_(zg);
                    creg[mi][p][ni] = c;
                    float h = og * tanh_(c);

                    if (store_lane) {
                        int j = jg + 2 * ni;
                        hnext[b * H_ + j] = __float2half(h);
                        out[((size_t)b * T_ + tt) * OW + dir * H_ + j] = h;
                    }
                }
            }
        }

        // xz prefetch for t+1
        if (t + 1 < T_) {
            const int tn = dir ? (T_ - 2 - t) : (t + 1);
            const float* xb = xzd + (size_t)tn * (B_ * G4) + n0 + c0;
            #pragma unroll
            for (int mi = 0; mi < 2; mi++)
                #pragma unroll
                for (int p = 0; p < 2; p++) {
                    int b = wm * 32 + mi * 16 + (lane >> 2) + 8 * p;
                    #pragma unroll
                    for (int ni = 0; ni < 2; ni++)
                        xzr[mi][p][ni] = __ldcs((const float2*)(xb + (size_t)b * G4 + ni * 8));
                }
        }

        // ---- per-direction grid barrier ----
        __syncthreads();
        if (tid == 0) {
            __threadfence();
            unsigned old = atomicAdd(&g_bar_cnt[dir], 1u);
            if (old == NBLK - 1) {
                g_bar_cnt[dir] = 0;
                __threadfence();
                atomicExch(&g_bar_gen[dir], bar_gen_seen + 1);
            } else {
                volatile unsigned* gen = (volatile unsigned*)&g_bar_gen[dir];
                while (*gen == bar_gen_seen) { }
                __threadfence();
            }
        }
        bar_gen_seen++;
        __syncthreads();
    }
}

// ---------------- launch ----------------------------------------------------
extern "C" void kernel_launch(void* const* d_in, const int* in_sizes, int n_in,
                              void* d_out, int out_size) {
    (void)in_sizes; (void)n_in; (void)out_size;
    const float* x  = (const float*)d_in[0];
    const float* Wf = (const float*)d_in[1];
    const float* Uf = (const float*)d_in[2];
    const float* bf = (const float*)d_in[3];
    const float* Wb = (const float*)d_in[4];
    const float* Ub = (const float*)d_in[5];
    const float* bb = (const float*)d_in[6];
    float* out = (float*)d_out;

    cudaFuncSetAttribute(rnn_persistent,
                         cudaFuncAttributeMaxDynamicSharedMemorySize, SMEM_BYTES);

    prep_w<<<(G4 * D_ + 255) / 256, 256>>>(Wf, Wb);
    prep_u<<<(H_ * G4 + 255) / 256, 256>>>(Uf, Ub);
    prep_state<<<(B_ * H_ + 255) / 256, 256>>>();

    proj_kernel<<<dim3(512, 24, 2), 256>>>(x, bf, bb);

    rnn_persistent<<<dim3(NBLK, 2), 256, SMEM_BYTES>>>(out);
}

// round 7
// speedup vs baseline: 3.6348x; 1.1757x over previous
#include <cuda_runtime.h>
#include <cuda_fp16.h>
#include <cstdint>
#include <cmath>

#define B_ 64
#define T_ 1024
#define D_ 512
#define H_ 768
#define G4 3072   // 4*H
#define OW 1536   // 2*H
#define NBD 64    // column blocks per direction
#define NTILE 48  // z-columns per block

// ---------------- scratch (device globals) ----------------------------------
__device__ __half   g_xzh[2][(size_t)T_ * B_ * G4];  // gate-permuted input proj, fp16
__device__ __half   g_xh[(size_t)B_ * T_ * D_];      // x converted to fp16
__device__ __half   g_Wph[2][(size_t)G4 * D_];       // permuted W, transposed [n][k]
__device__ __half   g_Ut[2][(size_t)G4 * H_];        // permuted U, transposed [n][k]
__device__ __half   g_h[2][2][B_ * H_];              // [dir][phase], fp16
__device__ unsigned g_bar_cnt[2];
__device__ unsigned g_bar_gen[2];

// ---------------- helpers --------------------------------------------------
__device__ __forceinline__ void mma_f16(float* c, const uint32_t* a,
                                        uint32_t b0, uint32_t b1) {
    asm volatile(
        "mma.sync.aligned.m16n8k16.row.col.f32.f16.f16.f32 "
        "{%0,%1,%2,%3}, {%4,%5,%6,%7}, {%8,%9}, {%0,%1,%2,%3};"
        : "+f"(c[0]), "+f"(c[1]), "+f"(c[2]), "+f"(c[3])
        : "r"(a[0]), "r"(a[1]), "r"(a[2]), "r"(a[3]), "r"(b0), "r"(b1));
}
__device__ __forceinline__ void ldsm_x4(uint32_t* r, uint32_t saddr) {
    asm volatile("ldmatrix.sync.aligned.m8n8.x4.shared.b16 {%0,%1,%2,%3}, [%4];"
        : "=r"(r[0]), "=r"(r[1]), "=r"(r[2]), "=r"(r[3]) : "r"(saddr));
}
__device__ __forceinline__ void ldsm_x2(uint32_t* r, uint32_t saddr) {
    asm volatile("ldmatrix.sync.aligned.m8n8.x2.shared.b16 {%0,%1}, [%2];"
        : "=r"(r[0]), "=r"(r[1]) : "r"(saddr));
}
__device__ __forceinline__ void cp_async16(uint32_t smem_u32, const void* gptr) {
    asm volatile("cp.async.cg.shared.global [%0], [%1], 16;"
                 :: "r"(smem_u32), "l"(gptr));
}
#define CP_COMMIT() asm volatile("cp.async.commit_group;")
#define CP_WAIT2()  asm volatile("cp.async.wait_group 2;")

__device__ __forceinline__ float ex2f(float x) {
    float r; asm("ex2.approx.f32 %0, %1;" : "=f"(r) : "f"(x)); return r;
}
__device__ __forceinline__ float rcpf(float x) {
    float r; asm("rcp.approx.f32 %0, %1;" : "=f"(r) : "f"(x)); return r;
}
#define L2E 1.4426950408889634f
__device__ __forceinline__ float sigm_(float x) { return rcpf(1.0f + ex2f(-x * L2E)); }
__device__ __forceinline__ float tanh_(float x) { return 1.0f - 2.0f * rcpf(1.0f + ex2f(2.0f * L2E * x)); }

// ---------------- prep kernels ---------------------------------------------
__global__ void prep_x(const float* __restrict__ x) {
    size_t i = (size_t)blockIdx.x * 256 + threadIdx.x;
    if (i >= (size_t)B_ * T_ * D_) return;
    g_xh[i] = __float2half(x[i]);
}

__global__ void prep_w(const float* __restrict__ Wf, const float* __restrict__ Wb) {
    int i = blockIdx.x * 256 + threadIdx.x;
    if (i >= G4 * D_) return;
    int n = i / D_;
    int k = i % D_;
    int src = k * G4 + (n & 3) * H_ + (n >> 2);
    g_Wph[0][i] = __float2half(Wf[src]);
    g_Wph[1][i] = __float2half(Wb[src]);
}

__global__ void prep_u(const float* __restrict__ Uf, const float* __restrict__ Ub) {
    int i = blockIdx.x * 256 + threadIdx.x;
    if (i >= H_ * G4) return;
    int n = i % G4;
    int k = i / G4;
    int src = k * G4 + (n & 3) * H_ + (n >> 2);
    g_Ut[0][(size_t)n * H_ + k] = __float2half(Uf[src]);
    g_Ut[1][(size_t)n * H_ + k] = __float2half(Ub[src]);
}

__global__ void prep_state() {
    int i = blockIdx.x * 256 + threadIdx.x;
    if (i >= B_ * H_) return;
    g_h[0][0][i] = __half(0.0f); g_h[0][1][i] = __half(0.0f);
    g_h[1][0][i] = __half(0.0f); g_h[1][1][i] = __half(0.0f);
}

// ---------------- input projection GEMM (fp16 in, fp16 out) -----------------
#define PJ_PAD 24

__global__ __launch_bounds__(256) void proj_kernel(const float* __restrict__ bfv,
                                                   const float* __restrict__ bbv) {
    __shared__ __half As[128][PJ_PAD];
    __shared__ __half Bs[128][PJ_PAD];

    const int dir = blockIdx.z;
    const __half* __restrict__ Wp = g_Wph[dir];
    const __half* __restrict__ xh = g_xh;
    const float* __restrict__ bias = dir ? bbv : bfv;
    const int row0 = blockIdx.x * 128;
    const int n0   = blockIdx.y * 128;
    const int tid  = threadIdx.x;
    const int lane = tid & 31;
    const int warp = tid >> 5;
    const int wm = warp & 1;
    const int wn = warp >> 1;

    const uint32_t As_base = (uint32_t)__cvta_generic_to_shared(&As[0][0]);
    const uint32_t Bs_base = (uint32_t)__cvta_generic_to_shared(&Bs[0][0]);
    const int lrow = lane & 15;
    const int lkc  = (lane >> 4) * 8;

    float acc[4][4][4];
    #pragma unroll
    for (int mi = 0; mi < 4; mi++)
        #pragma unroll
        for (int ni = 0; ni < 4; ni++)
            #pragma unroll
            for (int e = 0; e < 4; e++) acc[mi][ni][e] = 0.0f;

    for (int k0 = 0; k0 < D_; k0 += 16) {
        {   // A: 128 rows x 16 halves (fp16 x, 1 uint4 per thread)
            int row = tid >> 1;
            int c8 = (tid & 1) * 8;
            uint4 v = *(const uint4*)(xh + (size_t)(row0 + row) * D_ + k0 + c8);
            *(uint4*)&As[row][c8] = v;
        }
        {   // B: 128 n-rows x 16 halves
            int row = tid >> 1;
            int c8 = (tid & 1) * 8;
            uint4 v = *(const uint4*)(Wp + (size_t)(n0 + row) * D_ + k0 + c8);
            *(uint4*)&Bs[row][c8] = v;
        }
        __syncthreads();

        uint32_t bfr[4][2];
        #pragma unroll
        for (int np = 0; np < 2; np++) {
            uint32_t b4[4];
            ldsm_x4(b4, Bs_base + (uint32_t)(((wn * 32 + np * 16 + lrow) * PJ_PAD + lkc) * 2));
            bfr[np * 2 + 0][0] = b4[0]; bfr[np * 2 + 1][0] = b4[1];
            bfr[np * 2 + 0][1] = b4[2]; bfr[np * 2 + 1][1] = b4[3];
        }
        #pragma unroll
        for (int mi = 0; mi < 4; mi++) {
            uint32_t af[4];
            ldsm_x4(af, As_base + (uint32_t)(((wm * 64 + mi * 16 + lrow) * PJ_PAD + lkc) * 2));
            #pragma unroll
            for (int ni = 0; ni < 4; ni++)
                mma_f16(acc[mi][ni], af, bfr[ni][0], bfr[ni][1]);
        }
        __syncthreads();
    }

    #pragma unroll
    for (int mi = 0; mi < 4; mi++) {
        #pragma unroll
        for (int ni = 0; ni < 4; ni++) {
            int rl = wm * 64 + mi * 16 + (lane >> 2);
            int cl = wn * 32 + ni * 8 + 2 * (lane & 3);
            #pragma unroll
            for (int p = 0; p < 2; p++) {
                int rr = rl + p * 8;
                int grow = row0 + rr;
                int b = grow >> 10;
                int t = grow & (T_ - 1);
                int n = n0 + cl;
                float v0 = acc[mi][ni][2 * p + 0] + __ldg(&bias[(n & 3) * H_ + (n >> 2)]);
                float v1 = acc[mi][ni][2 * p + 1] + __ldg(&bias[((n + 1) & 3) * H_ + ((n + 1) >> 2)]);
                *(__half2*)&g_xzh[dir][((size_t)t * B_ + b) * G4 + n] =
                    __floats2half2_rn(v0, v1);
            }
        }
    }
}

// ---------------- persistent recurrent kernel -------------------------------
// 64 blocks/dir, each owns 48 z-cols (12 cells). Ut^T tile [48][768] fp16 in
// smem; h via 4-stage cp.async ring (k64 stages); warps wm4 x wn2 (m16 x n24).
#define UT_PAD   776                 // halves per Ut row
#define A_PAD    72                  // halves per A-stage row
#define SMEM_UT_HALVES (NTILE * UT_PAD)
#define SMEM_A_HALVES  (4 * 64 * A_PAD)
#define SMEM_BYTES_REAL ((SMEM_UT_HALVES + SMEM_A_HALVES) * 2)
#define SMEM_BYTES 118784   // pad to 116KB: forces occupancy 1 -> 1 block/SM

__global__ __launch_bounds__(256, 1) void rnn_persistent(float* __restrict__ out) {
    extern __shared__ char smem_raw[];
    __half* Us = (__half*)smem_raw;                              // [48][UT_PAD]
    __half* Ah = (__half*)(smem_raw + SMEM_UT_HALVES * 2);       // 4 stages [64][A_PAD]

    const int dir = blockIdx.y;
    const int n0  = blockIdx.x * NTILE;
    const int tid = threadIdx.x;
    const int lane = tid & 31;
    const int warp = tid >> 5;
    const int wm = warp & 3;     // 4 m-groups (batch rows)
    const int wn = warp >> 2;    // 2 n-groups (24 z-cols each)

    const __half* __restrict__ xzd = g_xzh[dir];

    // ---- load Ut tile once ----
    {
        const __half* src = g_Ut[dir] + (size_t)n0 * H_;
        for (int idx = tid; idx < NTILE * 96; idx += 256) {
            int n = idx / 96, ch = idx % 96;
            uint4 v = *(const uint4*)(src + (size_t)n * H_ + ch * 8);
            *(uint4*)(Us + n * UT_PAD + ch * 8) = v;
        }
    }
    __syncthreads();

    // cp.async geometry (64 rows x 64 halves per stage)
    const int ar   = tid >> 2;
    const int ac16 = (tid & 3) * 16;
    const uint32_t a_dst_base =
        (uint32_t)__cvta_generic_to_shared(Ah + ar * A_PAD + ac16);
    const uint32_t a_stage_stride = 64 * A_PAD * 2;

    // ldmatrix geometry
    const int lrow = lane & 15;
    const int lkc  = (lane >> 4) * 8;
    const int l15  = lane & 15;
    const uint32_t Ah_base = (uint32_t)__cvta_generic_to_shared(Ah);
    const uint32_t Us_base = (uint32_t)__cvta_generic_to_shared(Us);
    const uint32_t a_frag0 = Ah_base + (uint32_t)(((wm * 16 + lrow) * A_PAD + lkc) * 2);
    const uint32_t u4_base = Us_base + (uint32_t)(((wn * 24 + lrow) * UT_PAD + lkc) * 2);
    const uint32_t u2_base = Us_base + (uint32_t)(((wn * 24 + 16 + (l15 & 7)) * UT_PAD
                                                   + (l15 >> 3) * 8) * 2);

    // epilogue geometry
    const int c0 = wn * 24 + 2 * (lane & 3);
    const int jg = (n0 >> 2) + wn * 6 + ((lane & 3) >> 1);
    const bool store_lane = ((lane & 1) == 0);

    float creg[2][3];
    #pragma unroll
    for (int p = 0; p < 2; p++)
        #pragma unroll
        for (int ni = 0; ni < 3; ni++) creg[p][ni] = 0.0f;

    unsigned bar_gen_seen = g_bar_gen[dir];

    __half2 xzr[2][3];
    {
        const int tt0 = dir ? (T_ - 1) : 0;
        const __half* xb = xzd + (size_t)tt0 * (B_ * G4) + n0 + c0;
        #pragma unroll
        for (int p = 0; p < 2; p++) {
            int b = wm * 16 + (lane >> 2) + 8 * p;
            #pragma unroll
            for (int ni = 0; ni < 3; ni++)
                xzr[p][ni] = __ldcs((const __half2*)(xb + (size_t)b * G4 + ni * 8));
        }
    }

    for (int t = 0; t < T_; t++) {
        const __half* __restrict__ hp = g_h[dir][t & 1];
        __half* __restrict__ hnext = g_h[dir][(t + 1) & 1];
        const int tt = dir ? (T_ - 1 - t) : t;

        float acc[3][4];
        #pragma unroll
        for (int ni = 0; ni < 3; ni++)
            #pragma unroll
            for (int e = 0; e < 4; e++) acc[ni][e] = 0.0f;

        const char* hsrc = (const char*)(hp + (size_t)ar * H_ + ac16);

        #pragma unroll
        for (int s = 0; s < 3; s++) {
            cp_async16(a_dst_base + s * a_stage_stride, hsrc + (size_t)s * 128);
            cp_async16(a_dst_base + s * a_stage_stride + 16, hsrc + (size_t)s * 128 + 16);
            CP_COMMIT();
        }

        for (int i = 0; i < 12; i++) {     // k64 stages
            CP_WAIT2();
            __syncthreads();
            if (i < 9) {
                uint32_t d = a_dst_base + ((i + 3) & 3) * a_stage_stride;
                const char* s = hsrc + (size_t)(i + 3) * 128;
                cp_async16(d, s);
                cp_async16(d + 16, s + 16);
            }
            CP_COMMIT();

            const uint32_t a_st = a_frag0 + (uint32_t)(i & 3) * a_stage_stride;
            const uint32_t kb   = (uint32_t)(i * 128);   // i*64 halves in bytes
            #pragma unroll
            for (int ks = 0; ks < 4; ks++) {
                uint32_t b4[4], bx[2], af[4];
                ldsm_x4(b4, u4_base + kb + ks * 32);
                ldsm_x2(bx, u2_base + kb + ks * 32);
                ldsm_x4(af, a_st + ks * 32);
                mma_f16(acc[0], af, b4[0], b4[2]);
                mma_f16(acc[1], af, b4[1], b4[3]);
                mma_f16(acc[2], af, bx[0], bx[1]);
            }
        }

        // ---- epilogue in fragment layout ----
        #pragma unroll
        for (int p = 0; p < 2; p++) {
            int b = wm * 16 + (lane >> 2) + 8 * p;
            #pragma unroll
            for (int ni = 0; ni < 3; ni++) {
                float2 xf = __half22float2(xzr[p][ni]);
                float a0 = acc[ni][2 * p + 0] + xf.x;
                float a1 = acc[ni][2 * p + 1] + xf.y;
                float b0 = __shfl_xor_sync(0xffffffffu, a0, 1);
                float b1 = __shfl_xor_sync(0xffffffffu, a1, 1);
                bool oddl = lane & 1;
                float zi = oddl ? b0 : a0;
                float zf = oddl ? b1 : a1;
                float zg = oddl ? a0 : b0;
                float zo = oddl ? a1 : b1;

                float ig = sigm_(zi);
                float fg = sigm_(zf);
                float og = sigm_(zo);
                float c = fg * creg[p][ni] + ig * tanh_(zg);
                creg[p][ni] = c;
                float h = og * tanh_(c);

                if (store_lane) {
                    int j = jg + 2 * ni;
                    hnext[b * H_ + j] = __float2half(h);
                    out[((size_t)b * T_ + tt) * OW + dir * H_ + j] = h;
                }
            }
        }

        // xz prefetch for t+1
        if (t + 1 < T_) {
            const int tn = dir ? (T_ - 2 - t) : (t + 1);
            const __half* xb = xzd + (size_t)tn * (B_ * G4) + n0 + c0;
            #pragma unroll
            for (int p = 0; p < 2; p++) {
                int b = wm * 16 + (lane >> 2) + 8 * p;
                #pragma unroll
                for (int ni = 0; ni < 3; ni++)
                    xzr[p][ni] = __ldcs((const __half2*)(xb + (size_t)b * G4 + ni * 8));
            }
        }

        // ---- per-direction grid barrier (acq_rel atomics, no membar.gpu) ----
        __syncthreads();
        if (tid == 0) {
            unsigned old;
            asm volatile("atom.acq_rel.gpu.add.u32 %0, [%1], 1;"
                         : "=r"(old) : "l"(&g_bar_cnt[dir]) : "memory");
            if (old == NBD - 1) {
                asm volatile("st.relaxed.gpu.u32 [%0], 0;"
                             :: "l"(&g_bar_cnt[dir]) : "memory");
                asm volatile("st.release.gpu.u32 [%0], %1;"
                             :: "l"(&g_bar_gen[dir]), "r"(bar_gen_seen + 1) : "memory");
            } else {
                unsigned g;
                do {
                    asm volatile("ld.acquire.gpu.u32 %0, [%1];"
                                 : "=r"(g) : "l"(&g_bar_gen[dir]) : "memory");
                } while (g == bar_gen_seen);
            }
        }
        bar_gen_seen++;
        __syncthreads();
    }
}

// ---------------- launch ----------------------------------------------------
extern "C" void kernel_launch(void* const* d_in, const int* in_sizes, int n_in,
                              void* d_out, int out_size) {
    (void)in_sizes; (void)n_in; (void)out_size;
    const float* x  = (const float*)d_in[0];
    const float* Wf = (const float*)d_in[1];
    const float* Uf = (const float*)d_in[2];
    const float* bf = (const float*)d_in[3];
    const float* Wb = (const float*)d_in[4];
    const float* Ub = (const float*)d_in[5];
    const float* bb = (const float*)d_in[6];
    float* out = (float*)d_out;

    cudaFuncSetAttribute(rnn_persistent,
                         cudaFuncAttributeMaxDynamicSharedMemorySize, SMEM_BYTES);

    prep_x<<<(int)(((size_t)B_ * T_ * D_ + 255) / 256), 256>>>(x);
    prep_w<<<(G4 * D_ + 255) / 256, 256>>>(Wf, Wb);
    prep_u<<<(H_ * G4 + 255) / 256, 256>>>(Uf, Ub);
    prep_state<<<(B_ * H_ + 255) / 256, 256>>>();

    proj_kernel<<<dim3(512, 24, 2), 256>>>(bf, bb);

    rnn_persistent<<<dim3(NBD, 2), 256, SMEM_BYTES>>>(out);
}